// round 4
// baseline (speedup 1.0000x reference)
#include <cuda_runtime.h>
#include <cstdint>

// Shifted-window attention: B=32, W=8192, C=64, ws=64, shift=32.
// One CTA (64 threads) per window, 8x8 tile/thread, packed f32x2 FMA.
// Two shared buffers (A: Qt->Pt, B: Kt->V) => 33.3KB/CTA => 6 CTAs/SM.

#define TPB 64
#define NBLK 4096

#define SM_A 0        // Qt (gemm1) then Pt (gemm2): [d][r] swizzled
#define SM_B 4096     // Kt (gemm1) then V (gemm2)
#define SM_T 8192     // bias table (127 floats)
#define SM_FLOATS (8192 + 128)

__device__ __forceinline__ unsigned long long pk2(float x) {
    unsigned long long r;
    asm("mov.b64 %0, {%1, %1};" : "=l"(r) : "f"(x));
    return r;
}
__device__ __forceinline__ float2 unpk(unsigned long long v) {
    float2 r;
    asm("mov.b64 {%0, %1}, %2;" : "=f"(r.x), "=f"(r.y) : "l"(v));
    return r;
}
#define FMA2(acc, a, b) asm("fma.rn.f32x2 %0, %1, %2, %0;" : "+l"(acc) : "l"(a), "l"(b))

extern "C" __global__ void __launch_bounds__(TPB, 6)
win_attn_kernel(const float* __restrict__ q, const float* __restrict__ k,
                const float* __restrict__ v, const float* __restrict__ tab,
                float* __restrict__ out)
{
    extern __shared__ float sm[];
    const int tid = threadIdx.x;
    const int g   = blockIdx.x;
    const int bb  = g >> 7;          // batch
    const int w   = g & 127;         // window within batch
    const int start = w * 64 + 32;   // cyclic shift by -32 as gather
    const long batch_base = (long)bb * 8192;

    // ---- load Q,K window; transposed+swizzled: (d,p) -> d*64 + ((p>>2 + d>>2)&15)*4 + (p&3)
    #pragma unroll 4
    for (int it = 0; it < 16; ++it) {
        int idx = it * TPB + tid;    // 0..1023
        int p   = idx >> 4;          // window position 0..63
        int c4  = idx & 15;          // float4 chunk along head dim
        int row = (start + p) & 8191;
        long go = (batch_base + row) * 64 + c4 * 4;
        float4 qv = *(const float4*)(q + go);
        float4 kv = *(const float4*)(k + go);
        int off = (4 * c4) * 64 + ((((p >> 2) + c4) & 15) << 2) + (p & 3);
        float qa[4] = {qv.x, qv.y, qv.z, qv.w};
        float ka[4] = {kv.x, kv.y, kv.z, kv.w};
        #pragma unroll
        for (int e = 0; e < 4; ++e) {
            sm[SM_A + off + e * 64] = qa[e];
            sm[SM_B + off + e * 64] = ka[e];
        }
    }
    for (int i = tid; i < 127; i += TPB) sm[SM_T + i] = tab[i];
    __syncthreads();

    const int tx = tid & 7, ty = tid >> 3;
    // thread owns rows ty*8..+7, cols {4tx..4tx+3, 4tx+32..4tx+35}

    unsigned long long acc[32];
    #pragma unroll
    for (int i = 0; i < 32; ++i) acc[i] = 0ull;

    // ---- gemm1: S = Q K^T ----
    for (int d4 = 0; d4 < 16; ++d4) {
        int sa1 = ((2 * ty + d4) & 15) << 2;
        int sa2 = ((2 * ty + 1 + d4) & 15) << 2;
        int sb1 = ((tx + d4) & 15) << 2;
        int sb2 = ((tx + 8 + d4) & 15) << 2;
        const float* bA = sm + SM_A + d4 * 256;
        const float* bK = sm + SM_B + d4 * 256;
        #pragma unroll
        for (int e = 0; e < 4; ++e) {
            float4 a1 = *(const float4*)(bA + e * 64 + sa1);
            float4 a2 = *(const float4*)(bA + e * 64 + sa2);
            ulonglong2 b1 = *(const ulonglong2*)(bK + e * 64 + sb1);
            ulonglong2 b2 = *(const ulonglong2*)(bK + e * 64 + sb2);
            unsigned long long A[8] = {pk2(a1.x), pk2(a1.y), pk2(a1.z), pk2(a1.w),
                                       pk2(a2.x), pk2(a2.y), pk2(a2.z), pk2(a2.w)};
            #pragma unroll
            for (int i = 0; i < 8; ++i) {
                FMA2(acc[i * 4 + 0], A[i], b1.x);
                FMA2(acc[i * 4 + 1], A[i], b1.y);
                FMA2(acc[i * 4 + 2], A[i], b2.x);
                FMA2(acc[i * 4 + 3], A[i], b2.y);
            }
        }
    }

    // ---- V prefetch: issue LDGs now (independent of smem); STS after sync ----
    float4 vreg[8];
    #pragma unroll
    for (int it = 0; it < 8; ++it) {
        int idx = it * TPB + tid;            // first half: 512 chunks
        int p = idx >> 4, c4 = idx & 15;
        int row = (start + p) & 8191;
        vreg[it] = *(const float4*)(v + (batch_base + row) * 64 + c4 * 4);
    }

    // ---- epilogue: scale + bias + mask, softmax ----
    float s[8][8];
    #pragma unroll
    for (int i = 0; i < 8; ++i) {
        #pragma unroll
        for (int pp = 0; pp < 4; ++pp) {
            float2 u = unpk(acc[i * 4 + pp]);
            s[i][pp * 2] = u.x; s[i][pp * 2 + 1] = u.y;
        }
    }
    const float mkA = (w == 127 && ty >= 4) ? -100.0f : 0.0f;  // cols < 32
    const float mkB = (w == 127 && ty <  4) ? -100.0f : 0.0f;  // cols >= 32
    #pragma unroll
    for (int i = 0; i < 8; ++i) {
        int rbase = ty * 8 + i - 4 * tx + 63;
        #pragma unroll
        for (int j = 0; j < 8; ++j) {
            int coff = (j & 3) + ((j >> 2) << 5);
            s[i][j] = s[i][j] * 0.125f + sm[SM_T + rbase - coff] + ((j < 4) ? mkA : mkB);
        }
        float m = s[i][0];
        #pragma unroll
        for (int j = 1; j < 8; ++j) m = fmaxf(m, s[i][j]);
        m = fmaxf(m, __shfl_xor_sync(0xffffffffu, m, 1));
        m = fmaxf(m, __shfl_xor_sync(0xffffffffu, m, 2));
        m = fmaxf(m, __shfl_xor_sync(0xffffffffu, m, 4));
        float r = 0.0f;
        #pragma unroll
        for (int j = 0; j < 8; ++j) { s[i][j] = __expf(s[i][j] - m); r += s[i][j]; }
        r += __shfl_xor_sync(0xffffffffu, r, 1);
        r += __shfl_xor_sync(0xffffffffu, r, 2);
        r += __shfl_xor_sync(0xffffffffu, r, 4);
        float inv = __fdividef(1.0f, r);
        #pragma unroll
        for (int j = 0; j < 8; ++j) s[i][j] *= inv;
    }

    // ---- write attn (coalesced) ----
    {
        float* oat = out + (long)32 * 8192 * 64 + (long)g * 4096;
        #pragma unroll
        for (int i = 0; i < 8; ++i) {
            float* rp = oat + (ty * 8 + i) * 64;
            *(float4*)(rp + 4 * tx)      = make_float4(s[i][0], s[i][1], s[i][2], s[i][3]);
            *(float4*)(rp + 4 * tx + 32) = make_float4(s[i][4], s[i][5], s[i][6], s[i][7]);
        }
    }

    __syncthreads();   // Qt reads + Kt reads retired

    // ---- store V into buffer B (prefetched half + streamed half) ----
    #pragma unroll
    for (int it = 0; it < 8; ++it) {
        int idx = it * TPB + tid;
        int p = idx >> 4, c4 = idx & 15;
        *(float4*)&sm[SM_B + p * 64 + (((c4 + (p >> 2)) & 15) << 2)] = vreg[it];
    }
    #pragma unroll
    for (int it = 8; it < 16; ++it) {
        int idx = it * TPB + tid;
        int p = idx >> 4, c4 = idx & 15;
        int row = (start + p) & 8191;
        float4 vv = *(const float4*)(v + (batch_base + row) * 64 + c4 * 4);
        *(float4*)&sm[SM_B + p * 64 + (((c4 + (p >> 2)) & 15) << 2)] = vv;
    }

    // ---- store P transposed into buffer A: Pt[m][r] ----
    #pragma unroll
    for (int grp = 0; grp < 2; ++grp) {
        #pragma unroll
        for (int jj = 0; jj < 4; ++jj) {
            int m  = 4 * tx + 32 * grp + jj;
            int rm = tx + 8 * grp;          // m>>2
            int j  = grp * 4 + jj;
            float* bp = sm + SM_A + m * 64;
            *(float4*)(bp + (((2 * ty + rm) & 15) << 2)) =
                make_float4(s[0][j], s[1][j], s[2][j], s[3][j]);
            *(float4*)(bp + (((2 * ty + 1 + rm) & 15) << 2)) =
                make_float4(s[4][j], s[5][j], s[6][j], s[7][j]);
        }
    }
    __syncthreads();

    // ---- gemm2: O = P V ----
    #pragma unroll
    for (int i = 0; i < 32; ++i) acc[i] = 0ull;
    for (int d4 = 0; d4 < 16; ++d4) {
        int sa1 = ((2 * ty + d4) & 15) << 2;
        int sa2 = ((2 * ty + 1 + d4) & 15) << 2;
        int sb1 = ((tx + d4) & 15) << 2;
        int sb2 = ((tx + 8 + d4) & 15) << 2;
        const float* bA = sm + SM_A + d4 * 256;
        const float* bV = sm + SM_B + d4 * 256;
        #pragma unroll
        for (int e = 0; e < 4; ++e) {
            float4 a1 = *(const float4*)(bA + e * 64 + sa1);
            float4 a2 = *(const float4*)(bA + e * 64 + sa2);
            ulonglong2 b1 = *(const ulonglong2*)(bV + e * 64 + sb1);
            ulonglong2 b2 = *(const ulonglong2*)(bV + e * 64 + sb2);
            unsigned long long A[8] = {pk2(a1.x), pk2(a1.y), pk2(a1.z), pk2(a1.w),
                                       pk2(a2.x), pk2(a2.y), pk2(a2.z), pk2(a2.w)};
            #pragma unroll
            for (int i = 0; i < 8; ++i) {
                FMA2(acc[i * 4 + 0], A[i], b1.x);
                FMA2(acc[i * 4 + 1], A[i], b1.y);
                FMA2(acc[i * 4 + 2], A[i], b2.x);
                FMA2(acc[i * 4 + 3], A[i], b2.y);
            }
        }
    }

    // ---- write x with inverse cyclic shift (coalesced per row-group) ----
    #pragma unroll
    for (int i = 0; i < 8; ++i) {
        int row = (start + ty * 8 + i) & 8191;
        float* op = out + (batch_base + row) * 64;
        float2 u0 = unpk(acc[i * 4 + 0]);
        float2 u1 = unpk(acc[i * 4 + 1]);
        *(float4*)(op + 4 * tx) = make_float4(u0.x, u0.y, u1.x, u1.y);
        float2 u2 = unpk(acc[i * 4 + 2]);
        float2 u3 = unpk(acc[i * 4 + 3]);
        *(float4*)(op + 4 * tx + 32) = make_float4(u2.x, u2.y, u3.x, u3.y);
    }
}

extern "C" void kernel_launch(void* const* d_in, const int* in_sizes, int n_in,
                              void* d_out, int out_size)
{
    const float* q   = (const float*)d_in[0];
    const float* k   = (const float*)d_in[1];
    const float* v   = (const float*)d_in[2];
    const float* tab = (const float*)d_in[3];
    float* out = (float*)d_out;
    (void)in_sizes; (void)n_in; (void)out_size;

    size_t smem = SM_FLOATS * sizeof(float);   // 33280 B
    cudaFuncSetAttribute(win_attn_kernel,
                         cudaFuncAttributeMaxDynamicSharedMemorySize, (int)smem);
    win_attn_kernel<<<NBLK, TPB, smem>>>(q, k, v, tab, out);
}

// round 7
// speedup vs baseline: 1.3618x; 1.3618x over previous
#include <cuda_runtime.h>
#include <cuda_bf16.h>
#include <cstdint>

// Shifted-window attention via warp-level bf16 mma.sync (m16n8k16) with
// hi/lo split: X*Y ~= Xh*Yh + Xh*Yl + Xl*Yh. fp32 accumulate.
// B=32, W=8192, C=64, ws=64, shift=32. One CTA (128 thr) per window.
// Each warp owns 16 rows; no CTA-wide syncs after the load barrier.

#define TPB 128
#define NBLK 4096

// byte offsets in dynamic smem; each tile 64 rows x 128B (bf16 64x64)
#define SM_QH 0          // Qh then Ph
#define SM_QL 8192       // Ql then Pl
#define SM_KH 16384
#define SM_KL 24576
#define SM_VH 32768
#define SM_VL 40960
#define SM_BIAS 49152    // 127 floats
#define SM_TOTAL 49664

#define SWZ(x) ((x) ^ (((x) >> 3) & 0x70))

__device__ __forceinline__ uint32_t smem_u32(const void* p){
    uint32_t a;
    asm("{ .reg .u64 t; cvta.to.shared.u64 t, %1; cvt.u32.u64 %0, t; }" : "=r"(a) : "l"(p));
    return a;
}
// pack floats a(lo),b(hi) to bf16x2 hi-part and residual lo-part
__device__ __forceinline__ void split2(float a, float b, uint32_t& hi, uint32_t& lo){
    uint32_t h;
    asm("cvt.rn.bf16x2.f32 %0, %1, %2;" : "=r"(h) : "f"(b), "f"(a));
    float ha = __uint_as_float(h << 16);
    float hb = __uint_as_float(h & 0xffff0000u);
    uint32_t l;
    asm("cvt.rn.bf16x2.f32 %0, %1, %2;" : "=r"(l) : "f"(b - hb), "f"(a - ha));
    hi = h; lo = l;
}
#define LDSM_X4(r0,r1,r2,r3, a) \
    asm volatile("ldmatrix.sync.aligned.m8n8.x4.shared.b16 {%0,%1,%2,%3}, [%4];" \
        : "=r"(r0),"=r"(r1),"=r"(r2),"=r"(r3) : "r"(a))
#define LDSM_X4_T(r0,r1,r2,r3, a) \
    asm volatile("ldmatrix.sync.aligned.m8n8.x4.trans.shared.b16 {%0,%1,%2,%3}, [%4];" \
        : "=r"(r0),"=r"(r1),"=r"(r2),"=r"(r3) : "r"(a))
#define MMA(d, a0,a1,a2,a3, b0,b1) \
    asm volatile("mma.sync.aligned.m16n8k16.row.col.f32.bf16.bf16.f32 " \
        "{%0,%1,%2,%3}, {%4,%5,%6,%7}, {%8,%9}, {%0,%1,%2,%3};" \
        : "+f"((d)[0]),"+f"((d)[1]),"+f"((d)[2]),"+f"((d)[3]) \
        : "r"(a0),"r"(a1),"r"(a2),"r"(a3), "r"(b0),"r"(b1))

extern "C" __global__ void __launch_bounds__(TPB, 4)
win_attn_mma(const float* __restrict__ q, const float* __restrict__ k,
             const float* __restrict__ v, const float* __restrict__ tab,
             float* __restrict__ out)
{
    extern __shared__ __align__(128) char smem[];
    const uint32_t sb = smem_u32(smem);
    const int tid = threadIdx.x;
    const int g   = blockIdx.x;
    const int bb  = g >> 7;          // batch
    const int w   = g & 127;         // window
    const int start = w * 64 + 32;   // cyclic shift by -32 as gather
    const long batch_base = (long)bb * 8192;

    // ---- load Q,K,V window: fp32 -> bf16 hi/lo, swizzled 128B rows ----
    #pragma unroll
    for (int it = 0; it < 8; ++it) {
        int idx = it * TPB + tid;        // 0..1023
        int p = idx >> 4, c4 = idx & 15; // row p, cols 4c4..4c4+3
        int row = (start + p) & 8191;
        long go = (batch_base + row) * 64 + c4 * 4;
        uint32_t so = SWZ((uint32_t)(p * 128 + c4 * 8));
        float4 qv = *(const float4*)(q + go);
        float4 kv = *(const float4*)(k + go);
        float4 vv = *(const float4*)(v + go);
        uint32_t h0,l0,h1,l1;
        split2(qv.x, qv.y, h0, l0); split2(qv.z, qv.w, h1, l1);
        *(uint2*)(smem + SM_QH + so) = make_uint2(h0, h1);
        *(uint2*)(smem + SM_QL + so) = make_uint2(l0, l1);
        split2(kv.x, kv.y, h0, l0); split2(kv.z, kv.w, h1, l1);
        *(uint2*)(smem + SM_KH + so) = make_uint2(h0, h1);
        *(uint2*)(smem + SM_KL + so) = make_uint2(l0, l1);
        split2(vv.x, vv.y, h0, l0); split2(vv.z, vv.w, h1, l1);
        *(uint2*)(smem + SM_VH + so) = make_uint2(h0, h1);
        *(uint2*)(smem + SM_VL + so) = make_uint2(l0, l1);
    }
    if (tid < 127) ((float*)(smem + SM_BIAS))[tid] = tab[tid];
    __syncthreads();

    const int wid  = tid >> 5, lane = tid & 31;
    const int gq   = lane >> 2, t = lane & 3;
    const int R0   = wid * 16;
    const int r_lo = R0 + gq, r_hi = r_lo + 8;

    // A-frag ldmatrix address components (warp's own 16 rows)
    const uint32_t arow = (uint32_t)(R0 + (lane & 15));
    const uint32_t acol = (uint32_t)((lane >> 4) << 4);   // byte col block

    float acc[8][4];
    #pragma unroll
    for (int nt = 0; nt < 8; ++nt)
        #pragma unroll
        for (int e = 0; e < 4; ++e) acc[nt][e] = 0.0f;

    // ---- gemm1: S = Q K^T (hh + hl + lh) ----
    #pragma unroll
    for (int kc = 0; kc < 4; ++kc) {
        uint32_t aoff = SWZ(arow * 128 + (uint32_t)kc * 32 + acol);
        uint32_t ah0,ah1,ah2,ah3, al0,al1,al2,al3;
        LDSM_X4(ah0,ah1,ah2,ah3, sb + SM_QH + aoff);
        LDSM_X4(al0,al1,al2,al3, sb + SM_QL + aoff);
        // B: n from grp>>1, k-block from grp&1
        uint32_t grp = (uint32_t)(lane >> 3), l8 = (uint32_t)(lane & 7);
        uint32_t nrow_b = ((grp >> 1) << 3) + l8;
        uint32_t kcol_b = (uint32_t)kc * 32 + ((grp & 1) << 4);
        #pragma unroll
        for (int ntp = 0; ntp < 4; ++ntp) {
            uint32_t boff = SWZ((nrow_b + ntp * 16) * 128 + kcol_b);
            uint32_t bh0,bh1,bh2,bh3, bl0,bl1,bl2,bl3;
            LDSM_X4(bh0,bh1,bh2,bh3, sb + SM_KH + boff);
            LDSM_X4(bl0,bl1,bl2,bl3, sb + SM_KL + boff);
            MMA(acc[2*ntp],   ah0,ah1,ah2,ah3, bh0,bh1);
            MMA(acc[2*ntp],   ah0,ah1,ah2,ah3, bl0,bl1);
            MMA(acc[2*ntp],   al0,al1,al2,al3, bh0,bh1);
            MMA(acc[2*ntp+1], ah0,ah1,ah2,ah3, bh2,bh3);
            MMA(acc[2*ntp+1], ah0,ah1,ah2,ah3, bl2,bl3);
            MMA(acc[2*ntp+1], al0,al1,al2,al3, bh2,bh3);
        }
    }

    // ---- epilogue: scale + bias + mask, softmax over each row ----
    {
        const float* bt = (const float*)(smem + SM_BIAS);
        const bool dm = (w == 127);
        float mlo = -1e30f, mhi = -1e30f;
        #pragma unroll
        for (int nt = 0; nt < 8; ++nt) {
            int c0 = nt * 8 + 2 * t;
            float b0v = bt[r_lo - c0 + 63], b1v = bt[r_lo - c0 + 62];
            float b2v = bt[r_hi - c0 + 63], b3v = bt[r_hi - c0 + 62];
            float mk_lo = (dm && ((r_lo < 32) != (c0 < 32))) ? -100.0f : 0.0f;
            float mk_hi = (dm && ((r_hi < 32) != (c0 < 32))) ? -100.0f : 0.0f;
            acc[nt][0] = acc[nt][0] * 0.125f + b0v + mk_lo;
            acc[nt][1] = acc[nt][1] * 0.125f + b1v + mk_lo;
            acc[nt][2] = acc[nt][2] * 0.125f + b2v + mk_hi;
            acc[nt][3] = acc[nt][3] * 0.125f + b3v + mk_hi;
            mlo = fmaxf(mlo, fmaxf(acc[nt][0], acc[nt][1]));
            mhi = fmaxf(mhi, fmaxf(acc[nt][2], acc[nt][3]));
        }
        mlo = fmaxf(mlo, __shfl_xor_sync(0xffffffffu, mlo, 1));
        mlo = fmaxf(mlo, __shfl_xor_sync(0xffffffffu, mlo, 2));
        mhi = fmaxf(mhi, __shfl_xor_sync(0xffffffffu, mhi, 1));
        mhi = fmaxf(mhi, __shfl_xor_sync(0xffffffffu, mhi, 2));
        float slo = 0.0f, shi = 0.0f;
        #pragma unroll
        for (int nt = 0; nt < 8; ++nt) {
            acc[nt][0] = __expf(acc[nt][0] - mlo);
            acc[nt][1] = __expf(acc[nt][1] - mlo);
            acc[nt][2] = __expf(acc[nt][2] - mhi);
            acc[nt][3] = __expf(acc[nt][3] - mhi);
            slo += acc[nt][0] + acc[nt][1];
            shi += acc[nt][2] + acc[nt][3];
        }
        slo += __shfl_xor_sync(0xffffffffu, slo, 1);
        slo += __shfl_xor_sync(0xffffffffu, slo, 2);
        shi += __shfl_xor_sync(0xffffffffu, shi, 1);
        shi += __shfl_xor_sync(0xffffffffu, shi, 2);
        float ilo = __fdividef(1.0f, slo), ihi = __fdividef(1.0f, shi);
        #pragma unroll
        for (int nt = 0; nt < 8; ++nt) {
            acc[nt][0] *= ilo; acc[nt][1] *= ilo;
            acc[nt][2] *= ihi; acc[nt][3] *= ihi;
        }
    }

    // ---- write attn + store P (hi/lo) into Q buffers ----
    {
        float* oat = out + 16777216L + (long)g * 4096;
        #pragma unroll
        for (int nt = 0; nt < 8; ++nt) {
            int c0 = nt * 8 + 2 * t;
            *(float2*)(oat + r_lo * 64 + c0) = make_float2(acc[nt][0], acc[nt][1]);
            *(float2*)(oat + r_hi * 64 + c0) = make_float2(acc[nt][2], acc[nt][3]);
            uint32_t h, l;
            uint32_t so_lo = SWZ((uint32_t)(r_lo * 128 + c0 * 2));
            split2(acc[nt][0], acc[nt][1], h, l);
            *(uint32_t*)(smem + SM_QH + so_lo) = h;
            *(uint32_t*)(smem + SM_QL + so_lo) = l;
            uint32_t so_hi = SWZ((uint32_t)(r_hi * 128 + c0 * 2));
            split2(acc[nt][2], acc[nt][3], h, l);
            *(uint32_t*)(smem + SM_QH + so_hi) = h;
            *(uint32_t*)(smem + SM_QL + so_hi) = l;
        }
    }
    __syncwarp();   // P rows are warp-private; warp-level visibility suffices

    // ---- gemm2: O = P V (hh + hl + lh), V via ldmatrix.trans ----
    #pragma unroll
    for (int nt = 0; nt < 8; ++nt)
        #pragma unroll
        for (int e = 0; e < 4; ++e) acc[nt][e] = 0.0f;

    #pragma unroll
    for (int kc = 0; kc < 4; ++kc) {
        uint32_t aoff = SWZ(arow * 128 + (uint32_t)kc * 32 + acol);
        uint32_t ah0,ah1,ah2,ah3, al0,al1,al2,al3;
        LDSM_X4(ah0,ah1,ah2,ah3, sb + SM_QH + aoff);
        LDSM_X4(al0,al1,al2,al3, sb + SM_QL + aoff);
        uint32_t grp = (uint32_t)(lane >> 3), l8 = (uint32_t)(lane & 7);
        uint32_t krow = (uint32_t)kc * 16 + ((grp & 1) << 3) + l8;
        uint32_t nbase = ((grp >> 1) << 3);
        #pragma unroll
        for (int ntp = 0; ntp < 4; ++ntp) {
            uint32_t boff = SWZ(krow * 128 + (nbase + ntp * 16) * 2);
            uint32_t bh0,bh1,bh2,bh3, bl0,bl1,bl2,bl3;
            LDSM_X4_T(bh0,bh1,bh2,bh3, sb + SM_VH + boff);
            LDSM_X4_T(bl0,bl1,bl2,bl3, sb + SM_VL + boff);
            MMA(acc[2*ntp],   ah0,ah1,ah2,ah3, bh0,bh1);
            MMA(acc[2*ntp],   ah0,ah1,ah2,ah3, bl0,bl1);
            MMA(acc[2*ntp],   al0,al1,al2,al3, bh0,bh1);
            MMA(acc[2*ntp+1], ah0,ah1,ah2,ah3, bh2,bh3);
            MMA(acc[2*ntp+1], ah0,ah1,ah2,ah3, bl2,bl3);
            MMA(acc[2*ntp+1], al0,al1,al2,al3, bh2,bh3);
        }
    }

    // ---- write x with inverse cyclic shift ----
    {
        int row_lo = (start + r_lo) & 8191;
        int row_hi = (start + r_hi) & 8191;
        float* op_lo = out + (batch_base + row_lo) * 64;
        float* op_hi = out + (batch_base + row_hi) * 64;
        #pragma unroll
        for (int nt = 0; nt < 8; ++nt) {
            int c0 = nt * 8 + 2 * t;
            *(float2*)(op_lo + c0) = make_float2(acc[nt][0], acc[nt][1]);
            *(float2*)(op_hi + c0) = make_float2(acc[nt][2], acc[nt][3]);
        }
    }
}

extern "C" void kernel_launch(void* const* d_in, const int* in_sizes, int n_in,
                              void* d_out, int out_size)
{
    const float* q   = (const float*)d_in[0];
    const float* k   = (const float*)d_in[1];
    const float* v   = (const float*)d_in[2];
    const float* tab = (const float*)d_in[3];
    float* out = (float*)d_out;
    (void)in_sizes; (void)n_in; (void)out_size;

    cudaFuncSetAttribute(win_attn_mma,
                         cudaFuncAttributeMaxDynamicSharedMemorySize, SM_TOTAL);
    win_attn_mma<<<NBLK, TPB, SM_TOTAL>>>(q, k, v, tab, out);
}

// round 8
// speedup vs baseline: 1.6482x; 1.2103x over previous
#include <cuda_runtime.h>
#include <cuda_bf16.h>
#include <cstdint>

// Shifted-window attention via warp-level bf16 mma.sync (m16n8k16), hi/lo
// 3-product split. One CTA (128 thr) per window; warp owns 16 rows.
// Q loaded direct global->regs (warp-private A-frags); P kept in registers
// (acc layout == A-frag layout). Smem only for K and V hi/lo tiles.

#define TPB 128
#define NBLK 4096

#define SM_KH 0
#define SM_KL 8192
#define SM_VH 16384
#define SM_VL 24576
#define SM_BIAS 32768    // 127 floats
#define SM_TOTAL 33408

#define SWZ(x) ((x) ^ (((x) >> 3) & 0x70))

__device__ __forceinline__ uint32_t smem_u32(const void* p){
    uint32_t a;
    asm("{ .reg .u64 t; cvta.to.shared.u64 t, %1; cvt.u32.u64 %0, t; }" : "=r"(a) : "l"(p));
    return a;
}
// pack floats a(lo half),b(hi half) to bf16x2 hi-part and residual lo-part
__device__ __forceinline__ void split2(float a, float b, uint32_t& hi, uint32_t& lo){
    uint32_t h;
    asm("cvt.rn.bf16x2.f32 %0, %1, %2;" : "=r"(h) : "f"(b), "f"(a));
    float ha = __uint_as_float(h << 16);
    float hb = __uint_as_float(h & 0xffff0000u);
    uint32_t l;
    asm("cvt.rn.bf16x2.f32 %0, %1, %2;" : "=r"(l) : "f"(b - hb), "f"(a - ha));
    hi = h; lo = l;
}
#define LDSM_X4(r0,r1,r2,r3, a) \
    asm volatile("ldmatrix.sync.aligned.m8n8.x4.shared.b16 {%0,%1,%2,%3}, [%4];" \
        : "=r"(r0),"=r"(r1),"=r"(r2),"=r"(r3) : "r"(a))
#define LDSM_X4_T(r0,r1,r2,r3, a) \
    asm volatile("ldmatrix.sync.aligned.m8n8.x4.trans.shared.b16 {%0,%1,%2,%3}, [%4];" \
        : "=r"(r0),"=r"(r1),"=r"(r2),"=r"(r3) : "r"(a))
#define MMA(d, a0,a1,a2,a3, b0,b1) \
    asm volatile("mma.sync.aligned.m16n8k16.row.col.f32.bf16.bf16.f32 " \
        "{%0,%1,%2,%3}, {%4,%5,%6,%7}, {%8,%9}, {%0,%1,%2,%3};" \
        : "+f"((d)[0]),"+f"((d)[1]),"+f"((d)[2]),"+f"((d)[3]) \
        : "r"(a0),"r"(a1),"r"(a2),"r"(a3), "r"(b0),"r"(b1))

extern "C" __global__ void __launch_bounds__(TPB, 5)
win_attn_mma(const float* __restrict__ q, const float* __restrict__ k,
             const float* __restrict__ v, const float* __restrict__ tab,
             float* __restrict__ out)
{
    extern __shared__ __align__(128) char smem[];
    const uint32_t sb = smem_u32(smem);
    const int tid = threadIdx.x;
    const int g   = blockIdx.x;
    const int bb  = g >> 7;          // batch
    const int w   = g & 127;         // window
    const int start = w * 64 + 32;   // cyclic shift by -32 as gather
    const long batch_base = (long)bb * 8192;

    // ---- load K,V window: fp32 -> bf16 hi/lo, swizzled 128B rows ----
    #pragma unroll
    for (int it = 0; it < 8; ++it) {
        int idx = it * TPB + tid;        // 0..1023
        int p = idx >> 4, c4 = idx & 15; // row p, cols 4c4..4c4+3
        int row = (start + p) & 8191;
        long go = (batch_base + row) * 64 + c4 * 4;
        uint32_t so = SWZ((uint32_t)(p * 128 + c4 * 8));
        float4 kv = *(const float4*)(k + go);
        float4 vv = *(const float4*)(v + go);
        uint32_t h0,l0,h1,l1;
        split2(kv.x, kv.y, h0, l0); split2(kv.z, kv.w, h1, l1);
        *(uint2*)(smem + SM_KH + so) = make_uint2(h0, h1);
        *(uint2*)(smem + SM_KL + so) = make_uint2(l0, l1);
        split2(vv.x, vv.y, h0, l0); split2(vv.z, vv.w, h1, l1);
        *(uint2*)(smem + SM_VH + so) = make_uint2(h0, h1);
        *(uint2*)(smem + SM_VL + so) = make_uint2(l0, l1);
    }
    if (tid < 127) ((float*)(smem + SM_BIAS))[tid] = tab[tid];

    const int wid  = tid >> 5, lane = tid & 31;
    const int gq   = lane >> 2, t = lane & 3;
    const int R0   = wid * 16;
    const int r_lo = R0 + gq, r_hi = r_lo + 8;

    // ---- Q A-fragments: direct global loads (warp-private rows) ----
    const float* qlo = q + (batch_base + ((start + r_lo) & 8191)) * 64 + 2 * t;
    const float* qhi = q + (batch_base + ((start + r_hi) & 8191)) * 64 + 2 * t;
    uint32_t qah[16], qal[16];   // [kc*4 + {a0,a1,a2,a3}]
    #pragma unroll
    for (int kc = 0; kc < 4; ++kc) {
        float2 f0 = *(const float2*)(qlo + kc * 16);
        float2 f1 = *(const float2*)(qhi + kc * 16);
        float2 f2 = *(const float2*)(qlo + kc * 16 + 8);
        float2 f3 = *(const float2*)(qhi + kc * 16 + 8);
        split2(f0.x, f0.y, qah[kc*4+0], qal[kc*4+0]);
        split2(f1.x, f1.y, qah[kc*4+1], qal[kc*4+1]);
        split2(f2.x, f2.y, qah[kc*4+2], qal[kc*4+2]);
        split2(f3.x, f3.y, qah[kc*4+3], qal[kc*4+3]);
    }
    __syncthreads();

    float acc[8][4];
    #pragma unroll
    for (int nt = 0; nt < 8; ++nt)
        #pragma unroll
        for (int e = 0; e < 4; ++e) acc[nt][e] = 0.0f;

    // ---- gemm1: S = Q K^T (hh + hl + lh) ----
    #pragma unroll
    for (int kc = 0; kc < 4; ++kc) {
        uint32_t ah0 = qah[kc*4+0], ah1 = qah[kc*4+1], ah2 = qah[kc*4+2], ah3 = qah[kc*4+3];
        uint32_t al0 = qal[kc*4+0], al1 = qal[kc*4+1], al2 = qal[kc*4+2], al3 = qal[kc*4+3];
        uint32_t grp = (uint32_t)(lane >> 3), l8 = (uint32_t)(lane & 7);
        uint32_t nrow_b = ((grp >> 1) << 3) + l8;
        uint32_t kcol_b = (uint32_t)kc * 32 + ((grp & 1) << 4);
        #pragma unroll
        for (int ntp = 0; ntp < 4; ++ntp) {
            uint32_t boff = SWZ((nrow_b + ntp * 16) * 128 + kcol_b);
            uint32_t bh0,bh1,bh2,bh3, bl0,bl1,bl2,bl3;
            LDSM_X4(bh0,bh1,bh2,bh3, sb + SM_KH + boff);
            LDSM_X4(bl0,bl1,bl2,bl3, sb + SM_KL + boff);
            MMA(acc[2*ntp],   ah0,ah1,ah2,ah3, bh0,bh1);
            MMA(acc[2*ntp],   ah0,ah1,ah2,ah3, bl0,bl1);
            MMA(acc[2*ntp],   al0,al1,al2,al3, bh0,bh1);
            MMA(acc[2*ntp+1], ah0,ah1,ah2,ah3, bh2,bh3);
            MMA(acc[2*ntp+1], ah0,ah1,ah2,ah3, bl2,bl3);
            MMA(acc[2*ntp+1], al0,al1,al2,al3, bh2,bh3);
        }
    }

    // ---- epilogue: scale + bias + mask, softmax over each row ----
    {
        const float* bt = (const float*)(smem + SM_BIAS);
        const bool dm = (w == 127);
        float mlo = -1e30f, mhi = -1e30f;
        #pragma unroll
        for (int nt = 0; nt < 8; ++nt) {
            int c0 = nt * 8 + 2 * t;
            float b0v = bt[r_lo - c0 + 63], b1v = bt[r_lo - c0 + 62];
            float b2v = bt[r_hi - c0 + 63], b3v = bt[r_hi - c0 + 62];
            float mk_lo = (dm && ((r_lo < 32) != (c0 < 32))) ? -100.0f : 0.0f;
            float mk_hi = (dm && ((r_hi < 32) != (c0 < 32))) ? -100.0f : 0.0f;
            acc[nt][0] = acc[nt][0] * 0.125f + b0v + mk_lo;
            acc[nt][1] = acc[nt][1] * 0.125f + b1v + mk_lo;
            acc[nt][2] = acc[nt][2] * 0.125f + b2v + mk_hi;
            acc[nt][3] = acc[nt][3] * 0.125f + b3v + mk_hi;
            mlo = fmaxf(mlo, fmaxf(acc[nt][0], acc[nt][1]));
            mhi = fmaxf(mhi, fmaxf(acc[nt][2], acc[nt][3]));
        }
        mlo = fmaxf(mlo, __shfl_xor_sync(0xffffffffu, mlo, 1));
        mlo = fmaxf(mlo, __shfl_xor_sync(0xffffffffu, mlo, 2));
        mhi = fmaxf(mhi, __shfl_xor_sync(0xffffffffu, mhi, 1));
        mhi = fmaxf(mhi, __shfl_xor_sync(0xffffffffu, mhi, 2));
        float slo = 0.0f, shi = 0.0f;
        #pragma unroll
        for (int nt = 0; nt < 8; ++nt) {
            acc[nt][0] = __expf(acc[nt][0] - mlo);
            acc[nt][1] = __expf(acc[nt][1] - mlo);
            acc[nt][2] = __expf(acc[nt][2] - mhi);
            acc[nt][3] = __expf(acc[nt][3] - mhi);
            slo += acc[nt][0] + acc[nt][1];
            shi += acc[nt][2] + acc[nt][3];
        }
        slo += __shfl_xor_sync(0xffffffffu, slo, 1);
        slo += __shfl_xor_sync(0xffffffffu, slo, 2);
        shi += __shfl_xor_sync(0xffffffffu, shi, 1);
        shi += __shfl_xor_sync(0xffffffffu, shi, 2);
        float ilo = __fdividef(1.0f, slo), ihi = __fdividef(1.0f, shi);
        #pragma unroll
        for (int nt = 0; nt < 8; ++nt) {
            acc[nt][0] *= ilo; acc[nt][1] *= ilo;
            acc[nt][2] *= ihi; acc[nt][3] *= ihi;
        }
    }

    // ---- write attn ----
    {
        float* oat = out + 16777216L + (long)g * 4096;
        #pragma unroll
        for (int nt = 0; nt < 8; ++nt) {
            int c0 = nt * 8 + 2 * t;
            *(float2*)(oat + r_lo * 64 + c0) = make_float2(acc[nt][0], acc[nt][1]);
            *(float2*)(oat + r_hi * 64 + c0) = make_float2(acc[nt][2], acc[nt][3]);
        }
    }

    // ---- convert P (in acc) directly into gemm2 A-fragments ----
    // A-frag for k-chunk kc: a0=P[r_lo][16kc+2t,+1]=acc[2kc][0,1]
    //                        a1=acc[2kc][2,3]  a2=acc[2kc+1][0,1]  a3=acc[2kc+1][2,3]
    uint32_t pah[16], pal[16];
    #pragma unroll
    for (int kc = 0; kc < 4; ++kc) {
        split2(acc[2*kc][0],   acc[2*kc][1],   pah[kc*4+0], pal[kc*4+0]);
        split2(acc[2*kc][2],   acc[2*kc][3],   pah[kc*4+1], pal[kc*4+1]);
        split2(acc[2*kc+1][0], acc[2*kc+1][1], pah[kc*4+2], pal[kc*4+2]);
        split2(acc[2*kc+1][2], acc[2*kc+1][3], pah[kc*4+3], pal[kc*4+3]);
    }

    // ---- gemm2: O = P V (hh + hl + lh), V via ldmatrix.trans ----
    #pragma unroll
    for (int nt = 0; nt < 8; ++nt)
        #pragma unroll
        for (int e = 0; e < 4; ++e) acc[nt][e] = 0.0f;

    #pragma unroll
    for (int kc = 0; kc < 4; ++kc) {
        uint32_t ah0 = pah[kc*4+0], ah1 = pah[kc*4+1], ah2 = pah[kc*4+2], ah3 = pah[kc*4+3];
        uint32_t al0 = pal[kc*4+0], al1 = pal[kc*4+1], al2 = pal[kc*4+2], al3 = pal[kc*4+3];
        uint32_t grp = (uint32_t)(lane >> 3), l8 = (uint32_t)(lane & 7);
        uint32_t krow = (uint32_t)kc * 16 + ((grp & 1) << 3) + l8;
        uint32_t nbase = ((grp >> 1) << 3);
        #pragma unroll
        for (int ntp = 0; ntp < 4; ++ntp) {
            uint32_t boff = SWZ(krow * 128 + (nbase + ntp * 16) * 2);
            uint32_t bh0,bh1,bh2,bh3, bl0,bl1,bl2,bl3;
            LDSM_X4_T(bh0,bh1,bh2,bh3, sb + SM_VH + boff);
            LDSM_X4_T(bl0,bl1,bl2,bl3, sb + SM_VL + boff);
            MMA(acc[2*ntp],   ah0,ah1,ah2,ah3, bh0,bh1);
            MMA(acc[2*ntp],   ah0,ah1,ah2,ah3, bl0,bl1);
            MMA(acc[2*ntp],   al0,al1,al2,al3, bh0,bh1);
            MMA(acc[2*ntp+1], ah0,ah1,ah2,ah3, bh2,bh3);
            MMA(acc[2*ntp+1], ah0,ah1,ah2,ah3, bl2,bl3);
            MMA(acc[2*ntp+1], al0,al1,al2,al3, bh2,bh3);
        }
    }

    // ---- write x with inverse cyclic shift ----
    {
        int row_lo = (start + r_lo) & 8191;
        int row_hi = (start + r_hi) & 8191;
        float* op_lo = out + (batch_base + row_lo) * 64;
        float* op_hi = out + (batch_base + row_hi) * 64;
        #pragma unroll
        for (int nt = 0; nt < 8; ++nt) {
            int c0 = nt * 8 + 2 * t;
            *(float2*)(op_lo + c0) = make_float2(acc[nt][0], acc[nt][1]);
            *(float2*)(op_hi + c0) = make_float2(acc[nt][2], acc[nt][3]);
        }
    }
}

extern "C" void kernel_launch(void* const* d_in, const int* in_sizes, int n_in,
                              void* d_out, int out_size)
{
    const float* q   = (const float*)d_in[0];
    const float* k   = (const float*)d_in[1];
    const float* v   = (const float*)d_in[2];
    const float* tab = (const float*)d_in[3];
    float* out = (float*)d_out;
    (void)in_sizes; (void)n_in; (void)out_size;

    cudaFuncSetAttribute(win_attn_mma,
                         cudaFuncAttributeMaxDynamicSharedMemorySize, SM_TOTAL);
    win_attn_mma<<<NBLK, TPB, SM_TOTAL>>>(q, k, v, tab, out);
}